// round 4
// baseline (speedup 1.0000x reference)
#include <cuda_runtime.h>
#include <cstdint>

#define NB   16
#define NC   21
#define ND   512
#define HW   4096
#define NR   (NB*NC)   /* 336 */
#define RP   384
#define LABW 513
#define KSPL 16
#define NBLK 592       /* 148 SMs x 4 blocks, co-resident by construction */
#define NCH  256       /* label chunks: 16 per image, 256 px each */

// -------- device scratch (no allocations allowed) --------
__device__ unsigned char g_lab[NB * HW];        // resized labels, u8
__device__ int           g_cntC[NCH][NC];       // per-chunk class counts
__device__ unsigned char g_pres[NR];            // (b,c) presence
__device__ float         g_sums[NR * ND];       // pooled sums
__device__ float         g_P[RP * ND];          // normalized prototypes (padded)
__device__ float         g_S16[KSPL][RP * RP];  // k-split Gram partials
__device__ float         g_S[RP * RP];          // reduced Gram
__device__ unsigned int  g_barcnt = 0;
__device__ unsigned int  g_bargen = 0;

// -------- software grid barrier (all NBLK blocks co-resident) --------
__device__ __forceinline__ void gridbar()
{
    __syncthreads();
    if (threadIdx.x == 0) {
        __threadfence();
        unsigned gen = *(volatile unsigned*)&g_bargen;
        if (atomicAdd(&g_barcnt, 1u) == NBLK - 1) {
            g_barcnt = 0;
            __threadfence();
            *(volatile unsigned*)&g_bargen = gen + 1;
        } else {
            while (*(volatile unsigned*)&g_bargen == gen) __nanosleep(64);
        }
    }
    __syncthreads();
}

// -------- shared memory union (max member ~21.5 KB) --------
union SmU {
    struct { int scnt[NC]; } a;
    struct { float sacc[NC * 256]; } b;                    // 21504 B
    struct { float as[16][68]; float bs[16][68]; } d;      // 8704 B
    struct { float r0[256], r1[256], r2[256];
             unsigned char pres[NR]; } f;                  // 3408 B
};

__global__ __launch_bounds__(256, 4) void mono(const float* __restrict__ feat,
                                               const int* __restrict__ labels,
                                               float* __restrict__ out)
{
    __shared__ SmU sm;
    __shared__ float swred[8];
    const int bid = blockIdx.x;
    const int tid = threadIdx.x;

    if (bid == 0 && tid == 0) out[0] = 0.0f;

    // ================= Phase A: bilinear label resize + chunk counts ======
    if (bid < NCH) {
        if (tid < NC) sm.a.scnt[tid] = 0;
        __syncthreads();

        int b = bid >> 4, j = bid & 15;
        const int* lb = labels + (size_t)b * (LABW * LABW);
        int o  = j * 256 + tid;
        int oy = o >> 6, ox = o & 63;

        float sy  = __fsub_rn(__fmul_rn((float)oy + 0.5f, 8.015625f), 0.5f);
        int   y0  = (int)floorf(sy);
        float fy  = __fsub_rn(sy, (float)y0);
        float wy0 = __fsub_rn(1.0f, fy);
        float xy1 = __fsub_rn((float)(y0 + 1), sy);
        float wy1 = __fsub_rn(1.0f, xy1);
        float ty  = __fadd_rn(wy0, wy1);
        wy0 = __fdiv_rn(wy0, ty);
        wy1 = __fdiv_rn(wy1, ty);

        float sx  = __fsub_rn(__fmul_rn((float)ox + 0.5f, 8.015625f), 0.5f);
        int   x0  = (int)floorf(sx);
        float fx  = __fsub_rn(sx, (float)x0);
        float wx0 = __fsub_rn(1.0f, fx);
        float xx1 = __fsub_rn((float)(x0 + 1), sx);
        float wx1 = __fsub_rn(1.0f, xx1);
        float tx  = __fadd_rn(wx0, wx1);
        wx0 = __fdiv_rn(wx0, tx);
        wx1 = __fdiv_rn(wx1, tx);

        float v00 = (float)lb[y0 * LABW + x0];
        float v01 = (float)lb[y0 * LABW + x0 + 1];
        float v10 = (float)lb[(y0 + 1) * LABW + x0];
        float v11 = (float)lb[(y0 + 1) * LABW + x0 + 1];

        float t0 = __fadd_rn(__fmul_rn(wy0, v00), __fmul_rn(wy1, v10));
        float t1 = __fadd_rn(__fmul_rn(wy0, v01), __fmul_rn(wy1, v11));
        float v  = __fadd_rn(__fmul_rn(wx0, t0), __fmul_rn(wx1, t1));

        int li = (int)v;   // truncation toward zero
        g_lab[b * HW + o] = (unsigned char)li;
        atomicAdd(&sm.a.scnt[li], 1);
        __syncthreads();
        if (tid < NC) g_cntC[bid][tid] = sm.a.scnt[tid];
    }
    gridbar();

    // ================= Phase B: masked pooling (2 (b,d) per block) ========
    {
        const int h    = tid >> 7;       // which half
        const int t128 = tid & 127;
        for (int t = bid; t < NB * ND / 2; t += NBLK) {
            int bd = 2 * t + h;
            int b  = bd >> 9;

#pragma unroll
            for (int c = 0; c < NC; c++) sm.b.sacc[c * 256 + tid] = 0.0f;
            __syncthreads();

            const float4*       f4 = (const float4*)(feat + (size_t)bd * HW);
            const unsigned int* l4 = (const unsigned int*)g_lab + b * (HW / 4);

#pragma unroll
            for (int ch = 0; ch < 2; ch++) {
                float4       fv[4];
                unsigned int lv[4];
#pragma unroll
                for (int k = 0; k < 4; k++) {
                    fv[k] = f4[t128 + 128 * (ch * 4 + k)];
                    lv[k] = l4[t128 + 128 * (ch * 4 + k)];
                }
#pragma unroll
                for (int k = 0; k < 4; k++) {
                    unsigned int L = lv[k];
                    sm.b.sacc[((L      ) & 255u) * 256 + tid] += fv[k].x;
                    sm.b.sacc[((L >>  8) & 255u) * 256 + tid] += fv[k].y;
                    sm.b.sacc[((L >> 16) & 255u) * 256 + tid] += fv[k].z;
                    sm.b.sacc[((L >> 24) & 255u) * 256 + tid] += fv[k].w;
                }
            }
            __syncthreads();

            if (t128 < 84) {
                int c = t128 >> 2, part = t128 & 3;
                float s = 0.0f;
#pragma unroll
                for (int k = 0; k < 32; k++)
                    s += sm.b.sacc[c * 256 + h * 128 + part * 32 + k];
                unsigned m = __activemask();
                s += __shfl_xor_sync(m, s, 1);
                s += __shfl_xor_sync(m, s, 2);
                if (part == 0)
                    g_sums[(size_t)(b * NC + c) * ND + (bd & 511)] = s;
            }
            __syncthreads();
        }
    }
    gridbar();

    // ================= Phase C: normalize + presence reduce ===============
    if (bid < 192) {
        int h = tid >> 7, t128 = tid & 127;
        int r = 2 * bid + h;
        float4* dst = (float4*)(g_P + (size_t)r * ND);
        if (r >= NR) {
            dst[t128] = make_float4(0.f, 0.f, 0.f, 0.f);
        } else {
            const float4* src = (const float4*)(g_sums + (size_t)r * ND);
            float4 v = src[t128];
            float ss = v.x * v.x + v.y * v.y + v.z * v.z + v.w * v.w;
#pragma unroll
            for (int o = 16; o; o >>= 1) ss += __shfl_xor_sync(0xffffffffu, ss, o);
            if ((tid & 31) == 0) swred[tid >> 5] = ss;
            __syncthreads();
            float tot = swred[h * 4] + swred[h * 4 + 1] + swred[h * 4 + 2] + swred[h * 4 + 3];
            float den = fmaxf(sqrtf(tot), 1e-12f);
            float4 o4;
            o4.x = v.x / den; o4.y = v.y / den; o4.z = v.z / den; o4.w = v.w / den;
            dst[t128] = o4;
        }
    } else if (bid == 192) {
        for (int e = tid; e < NR; e += 256) {
            int b = e / NC, c = e - b * NC;
            int s = 0;
#pragma unroll
            for (int j = 0; j < 16; j++) s += g_cntC[b * 16 + j][c];
            g_pres[e] = (s > 0) ? 1 : 0;
        }
    }
    gridbar();

    // ================= Phase D: Gram = P*P^T (64x64 tiles, ksplit 16) =====
    if (bid < 36 * KSPL) {
        int tile = bid % 36, z = bid / 36;
        int m0 = (tile / 6) * 64, n0 = (tile % 6) * 64, k0 = z * 32;
        int tx = tid & 15, ty = tid >> 4;
        int lr = tid >> 2, lq = tid & 3;

        float acc[4][4] = {};

#pragma unroll
        for (int kt = 0; kt < 32; kt += 16) {
            float4 av = *(const float4*)&g_P[(size_t)(m0 + lr) * ND + k0 + kt + lq * 4];
            float4 bv = *(const float4*)&g_P[(size_t)(n0 + lr) * ND + k0 + kt + lq * 4];
            sm.d.as[lq * 4 + 0][lr] = av.x; sm.d.as[lq * 4 + 1][lr] = av.y;
            sm.d.as[lq * 4 + 2][lr] = av.z; sm.d.as[lq * 4 + 3][lr] = av.w;
            sm.d.bs[lq * 4 + 0][lr] = bv.x; sm.d.bs[lq * 4 + 1][lr] = bv.y;
            sm.d.bs[lq * 4 + 2][lr] = bv.z; sm.d.bs[lq * 4 + 3][lr] = bv.w;
            __syncthreads();
#pragma unroll
            for (int kk = 0; kk < 16; kk++) {
                float4 a  = *(const float4*)&sm.d.as[kk][ty * 4];
                float4 bb = *(const float4*)&sm.d.bs[kk][tx * 4];
                float ar[4] = {a.x, a.y, a.z, a.w};
                float br[4] = {bb.x, bb.y, bb.z, bb.w};
#pragma unroll
                for (int ia = 0; ia < 4; ia++)
#pragma unroll
                    for (int ib = 0; ib < 4; ib++)
                        acc[ia][ib] += ar[ia] * br[ib];
            }
            __syncthreads();
        }

        float* S = g_S16[z];
#pragma unroll
        for (int ia = 0; ia < 4; ia++) {
            float4 o = make_float4(acc[ia][0], acc[ia][1], acc[ia][2], acc[ia][3]);
            *(float4*)&S[(size_t)(m0 + ty * 4 + ia) * RP + n0 + tx * 4] = o;
        }
    }
    gridbar();

    // ================= Phase E: reduce 16 partials -> g_S =================
    {
        int idx = bid * 256 + tid;          // float4 index
        if (idx < RP * RP / 4) {
            float4 s = make_float4(0.f, 0.f, 0.f, 0.f);
#pragma unroll
            for (int p = 0; p < KSPL; p++) {
                float4 v = ((const float4*)g_S16[p])[idx];
                s.x += v.x; s.y += v.y; s.z += v.z; s.w += v.w;
            }
            ((float4*)g_S)[idx] = s;
        }
    }
    gridbar();

    // ================= Phase F: per-class masked LSE + pos mean ===========
    if (bid < NC) {
        int c = bid;
        for (int idx = tid; idx < NR; idx += 256) sm.f.pres[idx] = g_pres[idx];
        __syncthreads();

        int i = tid >> 4, j = tid & 15;
        float s_all = 0.f, s_diag = 0.f, p_sum = 0.f;
        int r1 = i * NC + c;
        if (sm.f.pres[r1]) {
            for (int e = 0; e < NC; e++) {
                int r2 = j * NC + e;
                if (sm.f.pres[r2]) {
                    float v = g_S[(size_t)r1 * RP + r2] / 0.1f;
                    float ev = expf(v);
                    s_all += ev;
                    if (e == c) { s_diag += ev; p_sum += v; }
                }
            }
        }
        sm.f.r0[tid] = s_all; sm.f.r1[tid] = s_diag; sm.f.r2[tid] = p_sum;
        __syncthreads();
        for (int st = 128; st; st >>= 1) {
            if (tid < st) {
                sm.f.r0[tid] += sm.f.r0[tid + st];
                sm.f.r1[tid] += sm.f.r1[tid + st];
                sm.f.r2[tid] += sm.f.r2[tid + st];
            }
            __syncthreads();
        }
        if (tid == 0) {
            int nc = 0;
            for (int ii = 0; ii < NB; ii++) nc += sm.f.pres[ii * NC + c];
            if (nc > 0) {
                float lse = logf(sm.f.r1[0] + sm.f.r0[0]);
                float pm  = sm.f.r2[0] / (float)(nc * nc);
                atomicAdd(out, lse - pm);
            }
        }
    }
}

// ============================================================
extern "C" void kernel_launch(void* const* d_in, const int* in_sizes, int n_in,
                              void* d_out, int out_size)
{
    const float* feat   = (const float*)d_in[0];
    const int*   labels = (const int*)d_in[1];
    float*       out    = (float*)d_out;

    mono<<<NBLK, 256>>>(feat, labels, out);
}

// round 5
// speedup vs baseline: 1.3459x; 1.3459x over previous
#include <cuda_runtime.h>
#include <cstdint>

#define NB   16
#define NC   21
#define ND   512
#define HW   4096
#define NR   (NB*NC)   /* 336 */
#define RP   384
#define LABW 513
#define KSPL 16

// -------- device scratch (no allocations allowed) --------
__device__ unsigned char g_lab[NB * HW];        // resized labels, u8
__device__ int           g_cntC[NB * 16][NC];   // per-chunk class counts
__device__ unsigned char g_pres[NR];            // (b,c) presence
__device__ float         g_sums[NR * ND];       // pooled sums
__device__ float         g_P[RP * ND];          // normalized prototypes (padded)
__device__ float         g_S[RP * RP];          // Gram (atomic-accumulated)

// ============================================================
// K1: bilinear label resize (jax.image.resize bilinear, antialias=False,
// fp32, H contracted first then W), per-chunk class counts, zero d_out.
// grid (16 images, 16 chunks) x 256 thr, 1 px/thread.
// ============================================================
__global__ __launch_bounds__(256) void k1_labels(const int* __restrict__ labels,
                                                 float* __restrict__ out)
{
    int b = blockIdx.x, j = blockIdx.y;
    int tid = threadIdx.x;
    __shared__ int scnt[NC];
    if (tid < NC) scnt[tid] = 0;
    __syncthreads();

    const int* lb = labels + (size_t)b * (LABW * LABW);
    int o  = j * 256 + tid;
    int oy = o >> 6, ox = o & 63;

    // ---- y weights (replicate jax compute_weight_mat, fp32) ----
    float sy  = __fsub_rn(__fmul_rn((float)oy + 0.5f, 8.015625f), 0.5f);
    int   y0  = (int)floorf(sy);
    float fy  = __fsub_rn(sy, (float)y0);
    float wy0 = __fsub_rn(1.0f, fy);
    float xy1 = __fsub_rn((float)(y0 + 1), sy);
    float wy1 = __fsub_rn(1.0f, xy1);
    float ty  = __fadd_rn(wy0, wy1);
    wy0 = __fdiv_rn(wy0, ty);
    wy1 = __fdiv_rn(wy1, ty);

    // ---- x weights ----
    float sx  = __fsub_rn(__fmul_rn((float)ox + 0.5f, 8.015625f), 0.5f);
    int   x0  = (int)floorf(sx);
    float fx  = __fsub_rn(sx, (float)x0);
    float wx0 = __fsub_rn(1.0f, fx);
    float xx1 = __fsub_rn((float)(x0 + 1), sx);
    float wx1 = __fsub_rn(1.0f, xx1);
    float tx  = __fadd_rn(wx0, wx1);
    wx0 = __fdiv_rn(wx0, tx);
    wx1 = __fdiv_rn(wx1, tx);

    float v00 = (float)lb[y0 * LABW + x0];
    float v01 = (float)lb[y0 * LABW + x0 + 1];
    float v10 = (float)lb[(y0 + 1) * LABW + x0];
    float v11 = (float)lb[(y0 + 1) * LABW + x0 + 1];

    // contract H first, then W (matches jax einsum dim order)
    float t0 = __fadd_rn(__fmul_rn(wy0, v00), __fmul_rn(wy1, v10));
    float t1 = __fadd_rn(__fmul_rn(wy0, v01), __fmul_rn(wy1, v11));
    float v  = __fadd_rn(__fmul_rn(wx0, t0), __fmul_rn(wx1, t1));

    int li = (int)v;   // truncation toward zero (values >= 0)
    g_lab[b * HW + o] = (unsigned char)li;
    atomicAdd(&scnt[li], 1);
    __syncthreads();
    if (tid < NC) g_cntC[b * 16 + j][tid] = scnt[tid];
    if (b == 0 && j == 0 && tid == 0) out[0] = 0.0f;
}

// ============================================================
// K2: masked pooling. One block per (b,d). 128 threads.
// Shared accumulators sacc[c*128+tid]: 128 % 32 == 0 ->
// bank = tid%32 for every class -> conflict-free, no atomics.
// Full-batch register prefetch (MLP 16/thread), 16 blocks/SM.
// ============================================================
__global__ __launch_bounds__(128) void k2_pool(const float* __restrict__ feat)
{
    __shared__ float sacc[NC * 128];
    int tid = threadIdx.x;
    int bd  = blockIdx.x;          // b*512 + d
    int b   = bd >> 9;

    // vectorized zero-init: NC*128 floats = 672 float4
    float4* z4 = (float4*)sacc;
#pragma unroll
    for (int i = 0; i < 6; i++) {
        int idx = tid + 128 * i;
        if (idx < NC * 32) z4[idx] = make_float4(0.f, 0.f, 0.f, 0.f);
    }
    __syncthreads();

    const float4*       f4 = (const float4*)(feat + (size_t)bd * HW);
    const unsigned int* l4 = (const unsigned int*)g_lab + b * (HW / 4);

    float4       fv[8];
    unsigned int lv[8];
#pragma unroll
    for (int k = 0; k < 8; k++) {
        fv[k] = f4[tid + 128 * k];
        lv[k] = l4[tid + 128 * k];
    }

#pragma unroll
    for (int k = 0; k < 8; k++) {
        unsigned int L = lv[k];
        sacc[((L      ) & 255u) * 128 + tid] += fv[k].x;
        sacc[((L >>  8) & 255u) * 128 + tid] += fv[k].y;
        sacc[((L >> 16) & 255u) * 128 + tid] += fv[k].z;
        sacc[((L >> 24) & 255u) * 128 + tid] += fv[k].w;
    }
    __syncthreads();

    // warp-parallel tail reduction: warp w handles classes w, w+4, ...
    int w = tid >> 5, l = tid & 31;
    for (int c = w; c < NC; c += 4) {
        const float* p = &sacc[c * 128 + l];
        float s = p[0] + p[32] + p[64] + p[96];
#pragma unroll
        for (int o = 16; o; o >>= 1) s += __shfl_xor_sync(0xffffffffu, s, o);
        if (l == 0)
            g_sums[(size_t)(b * NC + c) * ND + (bd & 511)] = s;
    }
}

// ============================================================
// K3: L2 normalize -> g_P; zero-fill padded rows 336..383;
// zero g_S; padding block 336 computes presence.
// ============================================================
__global__ __launch_bounds__(128) void k3_norm()
{
    int r = blockIdx.x, tid = threadIdx.x;

    // zero g_S: 36864 float4 / 384 blocks = 96 per block
    if (tid < 96)
        ((float4*)g_S)[r * 96 + tid] = make_float4(0.f, 0.f, 0.f, 0.f);

    float4* dst = (float4*)(g_P + (size_t)r * ND);
    if (r >= NR) {
        dst[tid] = make_float4(0.f, 0.f, 0.f, 0.f);
        if (r == NR) {   // presence reduce on one padding block
            for (int e = tid; e < NR; e += 128) {
                int b = e / NC, c = e - b * NC;
                int s = 0;
#pragma unroll
                for (int j = 0; j < 16; j++) s += g_cntC[b * 16 + j][c];
                g_pres[e] = (s > 0) ? 1 : 0;
            }
        }
        return;
    }
    const float4* src = (const float4*)(g_sums + (size_t)r * ND);
    float4 v = src[tid];
    float ss = v.x * v.x + v.y * v.y + v.z * v.z + v.w * v.w;
#pragma unroll
    for (int o = 16; o; o >>= 1) ss += __shfl_xor_sync(0xffffffffu, ss, o);
    __shared__ float sw[4];
    if ((tid & 31) == 0) sw[tid >> 5] = ss;
    __syncthreads();
    float tot = sw[0] + sw[1] + sw[2] + sw[3];
    float den = fmaxf(sqrtf(tot), 1e-12f);
    float4 o4;
    o4.x = v.x / den; o4.y = v.y / den; o4.z = v.z / den; o4.w = v.w / den;
    dst[tid] = o4;
}

// ============================================================
// K4: Gram = P * P^T, 64x64 tiles, 4x4 micro-tile, k-split 16,
// accumulated straight into g_S with atomicAdd (REDG, no return).
// ============================================================
__global__ __launch_bounds__(256) void k4_gemm()
{
    __shared__ float As[16][68];
    __shared__ float Bs[16][68];
    int tid = threadIdx.x;
    int tx = tid & 15, ty = tid >> 4;
    int m0 = blockIdx.y * 64, n0 = blockIdx.x * 64, k0 = blockIdx.z * 32;
    int lr = tid >> 2, lq = tid & 3;

    float acc[4][4] = {};

#pragma unroll
    for (int kt = 0; kt < 32; kt += 16) {
        float4 av = *(const float4*)&g_P[(size_t)(m0 + lr) * ND + k0 + kt + lq * 4];
        float4 bv = *(const float4*)&g_P[(size_t)(n0 + lr) * ND + k0 + kt + lq * 4];
        As[lq * 4 + 0][lr] = av.x; As[lq * 4 + 1][lr] = av.y;
        As[lq * 4 + 2][lr] = av.z; As[lq * 4 + 3][lr] = av.w;
        Bs[lq * 4 + 0][lr] = bv.x; Bs[lq * 4 + 1][lr] = bv.y;
        Bs[lq * 4 + 2][lr] = bv.z; Bs[lq * 4 + 3][lr] = bv.w;
        __syncthreads();
#pragma unroll
        for (int kk = 0; kk < 16; kk++) {
            float4 a  = *(const float4*)&As[kk][ty * 4];
            float4 bb = *(const float4*)&Bs[kk][tx * 4];
            float ar[4] = {a.x, a.y, a.z, a.w};
            float br[4] = {bb.x, bb.y, bb.z, bb.w};
#pragma unroll
            for (int ia = 0; ia < 4; ia++)
#pragma unroll
                for (int ib = 0; ib < 4; ib++)
                    acc[ia][ib] += ar[ia] * br[ib];
        }
        __syncthreads();
    }

#pragma unroll
    for (int ia = 0; ia < 4; ia++)
#pragma unroll
        for (int ib = 0; ib < 4; ib++)
            atomicAdd(&g_S[(size_t)(m0 + ty * 4 + ia) * RP + n0 + tx * 4 + ib],
                      acc[ia][ib]);
}

// ============================================================
// K5: per-class masked LSE + positive mean -> atomicAdd loss
// ============================================================
__global__ __launch_bounds__(256) void k5_loss(float* __restrict__ out)
{
    __shared__ unsigned char pres[NR];
    __shared__ float red0[256], red1[256], red2[256];
    int tid = threadIdx.x;
    int c = blockIdx.x;
    for (int idx = tid; idx < NR; idx += 256) pres[idx] = g_pres[idx];
    __syncthreads();

    int i = tid >> 4, j = tid & 15;
    float s_all = 0.f, s_diag = 0.f, p_sum = 0.f;
    int r1 = i * NC + c;
    if (pres[r1]) {
        for (int e = 0; e < NC; e++) {
            int r2 = j * NC + e;
            if (pres[r2]) {
                float v = g_S[(size_t)r1 * RP + r2] / 0.1f;
                float ev = expf(v);
                s_all += ev;
                if (e == c) { s_diag += ev; p_sum += v; }
            }
        }
    }
    red0[tid] = s_all; red1[tid] = s_diag; red2[tid] = p_sum;
    __syncthreads();
    for (int st = 128; st; st >>= 1) {
        if (tid < st) {
            red0[tid] += red0[tid + st];
            red1[tid] += red1[tid + st];
            red2[tid] += red2[tid + st];
        }
        __syncthreads();
    }
    if (tid == 0) {
        int nc = 0;
        for (int ii = 0; ii < NB; ii++) nc += pres[ii * NC + c];
        if (nc > 0) {
            float lse = logf(red1[0] + red0[0]);   // logaddexp(lse_diag, lse_all)
            float pm  = red2[0] / (float)(nc * nc);
            atomicAdd(out, lse - pm);
        }
    }
}

// ============================================================
extern "C" void kernel_launch(void* const* d_in, const int* in_sizes, int n_in,
                              void* d_out, int out_size)
{
    const float* feat   = (const float*)d_in[0];
    const int*   labels = (const int*)d_in[1];
    float*       out    = (float*)d_out;

    k1_labels<<<dim3(NB, 16), 256>>>(labels, out);
    k2_pool<<<NB * ND, 128>>>(feat);
    k3_norm<<<RP, 128>>>();
    k4_gemm<<<dim3(6, 6, KSPL), 256>>>();
    k5_loss<<<NC, 256>>>(out);
}